// round 9
// baseline (speedup 1.0000x reference)
#include <cuda_runtime.h>
#include <cuda_fp16.h>
#include <cstdint>

// B=16384, N=64, D=64, O=64
// softmax(others@a2 + robot@a1) == softmax(others@a2)  (robot term constant)
// out = elu( diag(1,attn) @ (h@W) )   -- attn folded into the epilogue
// 128-thread CTA, 4 warps: warp w -> rows [16w,16w+16) x ALL 64 cols.
// Every h element passes through LDS exactly once; v2 held in registers.
// fp16 m16n8k16 GEMM, B-fragments in registers (64), cp.async double buffer.

#define GB 8      // batches per CTA
#define HS 80     // h smem row stride (floats): conflict-free float4 phases

__device__ __forceinline__ unsigned h2u(__half2 h) {
    return *reinterpret_cast<unsigned*>(&h);
}

__device__ __forceinline__ float elu1(float x) {
    return x > 0.f ? x : (__expf(x) - 1.f);
}

__device__ __forceinline__ void cp_async16(uint32_t saddr, const void* gptr) {
    asm volatile("cp.async.cg.shared.global [%0], [%1], 16;\n"
                 :: "r"(saddr), "l"(gptr));
}

__global__ __launch_bounds__(128)
void gat_fused_kernel(const float* __restrict__ h,
                      const float* __restrict__ W,
                      const float* __restrict__ a,
                      float* __restrict__ out) {
    __shared__ float sh[2][64 * HS];            // double-buffered h (fp32)
    __shared__ float sdots[64];
    __shared__ __align__(16) float sv2[64];

    const int tid  = threadIdx.x;
    const int lane = tid & 31;
    const int warp = tid >> 5;     // 0..3 = m-tile
    const int gid  = lane >> 2;    // 0..7
    const int tig  = lane & 3;     // 0..3

    // ---- B-fragments (fp16) into registers, once ----
    // K-perm within slab q: actual col 16q+4t+j <-> mma-k {2t,2t+1,2t+8,2t+9}
    // N-perm: tile nt, local n -> col (nt>>1)*16 + (n>>1)*4 + (nt&1)*2 + (n&1)
    unsigned bfr[4][8][2];
    {
#pragma unroll
        for (int q = 0; q < 4; ++q) {
            const int kr = 16 * q + 4 * tig;
#pragma unroll
            for (int nt = 0; nt < 8; ++nt) {
                int col = (nt >> 1) * 16 + (gid >> 1) * 4
                        + (nt & 1) * 2 + (gid & 1);
                bfr[q][nt][0] = h2u(__floats2half2_rn(W[kr * 64 + col],
                                                      W[(kr + 1) * 64 + col]));
                bfr[q][nt][1] = h2u(__floats2half2_rn(W[(kr + 2) * 64 + col],
                                                      W[(kr + 3) * 64 + col]));
            }
        }
    }

    // ---- v2 = W @ a2 (threads 0..63) ----
    if (tid < 64) {
        const float* a2 = a + 64;
        float s = 0.f;
#pragma unroll
        for (int o = 0; o < 64; ++o) s = fmaf(W[tid * 64 + o], a2[o], s);
        sv2[tid] = s;
    }
    __syncthreads();

    // v2 values this thread needs (cols 16q+4tig..+3), loop-invariant
    float4 vv[4];
#pragma unroll
    for (int q = 0; q < 4; ++q)
        vv[q] = *reinterpret_cast<const float4*>(&sv2[16 * q + 4 * tig]);

    const size_t base = (size_t)blockIdx.x * GB * 4096;

    // ---- prefetch batch 0 ----
    {
        const float* hb = h + base;
        uint32_t sb = (uint32_t)__cvta_generic_to_shared(&sh[0][0]);
#pragma unroll
        for (int c = tid; c < 1024; c += 128) {
            int row = c >> 4, q = c & 15;
            cp_async16(sb + (row * HS + q * 4) * 4, hb + c * 4);
        }
        asm volatile("cp.async.commit_group;\n");
    }

    const int rA = warp * 16 + gid;   // this thread's two rows
    const int rB = rA + 8;

    for (int g = 0; g < GB; ++g) {
        const int buf = g & 1;

        asm volatile("cp.async.wait_group 0;\n");
        __syncthreads();   // buf[g] ready; prev iter's sdots reads done

        // ---- prefetch batch g+1 ----
        if (g + 1 < GB) {
            const float* hb = h + base + (size_t)(g + 1) * 4096;
            uint32_t sb = (uint32_t)__cvta_generic_to_shared(&sh[buf ^ 1][0]);
#pragma unroll
            for (int c = tid; c < 1024; c += 128) {
                int row = c >> 4, q = c & 15;
                cp_async16(sb + (row * HS + q * 4) * 4, hb + c * 4);
            }
            asm volatile("cp.async.commit_group;\n");
        }

        // ---- GEMM (fp16, unscaled, 8 n-tiles) + fp32 dot partials ----
        float acc[8][4];
#pragma unroll
        for (int nt = 0; nt < 8; ++nt)
#pragma unroll
            for (int k = 0; k < 4; ++k) acc[nt][k] = 0.f;

        float pd0 = 0.f, pd1 = 0.f;
        const float* shb = &sh[buf][0];

#pragma unroll
        for (int q = 0; q < 4; ++q) {
            const int cb = 16 * q + 4 * tig;
            const float4 vA = *reinterpret_cast<const float4*>(&shb[rA * HS + cb]);
            const float4 vB = *reinterpret_cast<const float4*>(&shb[rB * HS + cb]);

            pd0 = fmaf(vA.x, vv[q].x, fmaf(vA.y, vv[q].y,
                  fmaf(vA.z, vv[q].z, fmaf(vA.w, vv[q].w, pd0))));
            pd1 = fmaf(vB.x, vv[q].x, fmaf(vB.y, vv[q].y,
                  fmaf(vB.z, vv[q].z, fmaf(vB.w, vv[q].w, pd1))));

            unsigned a0 = h2u(__floats2half2_rn(vA.x, vA.y));
            unsigned a1 = h2u(__floats2half2_rn(vB.x, vB.y));
            unsigned a2 = h2u(__floats2half2_rn(vA.z, vA.w));
            unsigned a3 = h2u(__floats2half2_rn(vB.z, vB.w));
#pragma unroll
            for (int nt = 0; nt < 8; ++nt) {
                asm volatile(
                    "mma.sync.aligned.m16n8k16.row.col.f32.f16.f16.f32 "
                    "{%0,%1,%2,%3}, {%4,%5,%6,%7}, {%8,%9}, {%0,%1,%2,%3};"
                    : "+f"(acc[nt][0]), "+f"(acc[nt][1]),
                      "+f"(acc[nt][2]), "+f"(acc[nt][3])
                    : "r"(a0), "r"(a1), "r"(a2), "r"(a3),
                      "r"(bfr[q][nt][0]), "r"(bfr[q][nt][1]));
            }
        }

        // ---- reduce dots over tig lanes; publish ----
        pd0 += __shfl_xor_sync(0xffffffffu, pd0, 1);
        pd0 += __shfl_xor_sync(0xffffffffu, pd0, 2);
        pd1 += __shfl_xor_sync(0xffffffffu, pd1, 1);
        pd1 += __shfl_xor_sync(0xffffffffu, pd1, 2);
        if (tig == 0) {
            sdots[rA] = pd0;
            sdots[rB] = pd1;
        }
        __syncthreads();   // sdots complete

        // ---- warp-local softmax over rows 1..63 ----
        float x0 = (lane >= 1) ? sdots[lane] : -1e30f;
        float x1 = sdots[lane + 32];
        float m = fmaxf(x0, x1);
#pragma unroll
        for (int off = 16; off; off >>= 1)
            m = fmaxf(m, __shfl_xor_sync(0xffffffffu, m, off));
        float e0s = (lane >= 1) ? __expf(x0 - m) : 0.f;
        float e1s = __expf(x1 - m);
        float s = e0s + e1s;
#pragma unroll
        for (int off = 16; off; off >>= 1)
            s += __shfl_xor_sync(0xffffffffu, s, off);
        const float inv = 1.f / s;

        const float fA = (rA == 0) ? 1.f : __expf(pd0 - m) * inv;
        const float fB = __expf(pd1 - m) * inv;   // rB >= 8, never robot

        // ---- epilogue: scale, elu, 8x STG.128 ----
        float* ob = out + base + (size_t)g * 4096;
#pragma unroll
        for (int p = 0; p < 4; ++p) {
            const int col = p * 16 + tig * 4;
            float4 v0 = make_float4(elu1(acc[2 * p][0] * fA),
                                    elu1(acc[2 * p][1] * fA),
                                    elu1(acc[2 * p + 1][0] * fA),
                                    elu1(acc[2 * p + 1][1] * fA));
            float4 v1 = make_float4(elu1(acc[2 * p][2] * fB),
                                    elu1(acc[2 * p][3] * fB),
                                    elu1(acc[2 * p + 1][2] * fB),
                                    elu1(acc[2 * p + 1][3] * fB));
            *reinterpret_cast<float4*>(ob + rA * 64 + col) = v0;
            *reinterpret_cast<float4*>(ob + rB * 64 + col) = v1;
        }
    }
}

extern "C" void kernel_launch(void* const* d_in, const int* in_sizes, int n_in,
                              void* d_out, int out_size) {
    const float* h = (const float*)d_in[0];   // (16384, 64, 64) f32
    const float* W = (const float*)d_in[1];   // (64, 64) f32
    const float* a = (const float*)d_in[2];   // (128, 1) f32
    float* out = (float*)d_out;               // (16384, 64, 64) f32

    gat_fused_kernel<<<16384 / GB, 128>>>(h, W, a, out);
}

// round 10
// speedup vs baseline: 1.0766x; 1.0766x over previous
#include <cuda_runtime.h>
#include <cuda_fp16.h>
#include <cstdint>

// B=16384, N=64, D=64, O=64
// softmax(others@a2 + robot@a1) == softmax(others@a2)  (robot term constant)
// out = elu( diag(1,attn) @ (h@W) )   -- attn folded into the epilogue
// 128-thread CTA, 4 warps: warp w -> rows [16w,16w+16) x ALL 64 cols (h read
// once). fp16 m16n8k16 GEMM, B-frags in registers. TRIPLE-buffered h smem,
// prefetch 2 batches ahead (cp.async, wait_group 1) for 2x memory in flight.

#define GB 8      // batches per CTA
#define HS 80     // h smem row stride (floats): conflict-free float4 phases
#define NBUF 3

#define SMEM_FLOATS (NBUF * 64 * HS + 2 * 64 + 64)

__device__ __forceinline__ unsigned h2u(__half2 h) {
    return *reinterpret_cast<unsigned*>(&h);
}

__device__ __forceinline__ float elu1(float x) {
    return x > 0.f ? x : (__expf(x) - 1.f);
}

__device__ __forceinline__ void cp_async16(uint32_t saddr, const void* gptr) {
    asm volatile("cp.async.cg.shared.global [%0], [%1], 16;\n"
                 :: "r"(saddr), "l"(gptr));
}

__global__ __launch_bounds__(128)
void gat_fused_kernel(const float* __restrict__ h,
                      const float* __restrict__ W,
                      const float* __restrict__ a,
                      float* __restrict__ out) {
    extern __shared__ float smem[];
    float* shbase = smem;                       // [NBUF][64*HS]
    float* sdots  = smem + NBUF * 64 * HS;      // [2][64]
    float* sv2    = sdots + 128;                // [64], 16B-aligned

    const int tid  = threadIdx.x;
    const int lane = tid & 31;
    const int warp = tid >> 5;     // 0..3 = m-tile
    const int gid  = lane >> 2;    // 0..7
    const int tig  = lane & 3;     // 0..3

    // ---- B-fragments (fp16) into registers, once ----
    // K-perm within slab q: actual col 16q+4t+j <-> mma-k {2t,2t+1,2t+8,2t+9}
    // N-perm: tile nt, local n -> col (nt>>1)*16 + (n>>1)*4 + (nt&1)*2 + (n&1)
    unsigned bfr[4][8][2];
#pragma unroll
    for (int q = 0; q < 4; ++q) {
        const int kr = 16 * q + 4 * tig;
#pragma unroll
        for (int nt = 0; nt < 8; ++nt) {
            int col = (nt >> 1) * 16 + (gid >> 1) * 4 + (nt & 1) * 2 + (gid & 1);
            bfr[q][nt][0] = h2u(__floats2half2_rn(W[kr * 64 + col],
                                                  W[(kr + 1) * 64 + col]));
            bfr[q][nt][1] = h2u(__floats2half2_rn(W[(kr + 2) * 64 + col],
                                                  W[(kr + 3) * 64 + col]));
        }
    }

    // ---- v2 = W @ a2 (threads 0..63) ----
    if (tid < 64) {
        const float* a2 = a + 64;
        float s = 0.f;
#pragma unroll
        for (int o = 0; o < 64; ++o) s = fmaf(W[tid * 64 + o], a2[o], s);
        sv2[tid] = s;
    }
    __syncthreads();

    // v2 values this thread needs (cols 16q+4tig..+3), loop-invariant
    float4 vv[4];
#pragma unroll
    for (int q = 0; q < 4; ++q)
        vv[q] = *reinterpret_cast<const float4*>(&sv2[16 * q + 4 * tig]);

    const size_t base = (size_t)blockIdx.x * GB * 4096;

    // ---- prefetch batches 0 and 1 (two commit groups) ----
#pragma unroll
    for (int p = 0; p < 2; ++p) {
        const float* hb = h + base + (size_t)p * 4096;
        uint32_t sb = (uint32_t)__cvta_generic_to_shared(&shbase[p * 64 * HS]);
#pragma unroll
        for (int c = tid; c < 1024; c += 128) {
            int row = c >> 4, q = c & 15;
            cp_async16(sb + (row * HS + q * 4) * 4, hb + c * 4);
        }
        asm volatile("cp.async.commit_group;\n");
    }

    const int rA = warp * 16 + gid;   // this thread's two rows
    const int rB = rA + 8;

    for (int g = 0; g < GB; ++g) {
        // wait until batch g's copy (oldest group) is done
        if (g + 2 < GB)
            asm volatile("cp.async.wait_group 1;\n");
        else
            asm volatile("cp.async.wait_group 0;\n");
        __syncthreads();   // bar A: buffer g visible to all; buffer (g+2)%3 free

        // ---- prefetch batch g+2 into buffer (g+2)%NBUF ----
        if (g + 2 < GB) {
            const float* hb = h + base + (size_t)(g + 2) * 4096;
            uint32_t sb = (uint32_t)__cvta_generic_to_shared(
                              &shbase[((g + 2) % NBUF) * 64 * HS]);
#pragma unroll
            for (int c = tid; c < 1024; c += 128) {
                int row = c >> 4, q = c & 15;
                cp_async16(sb + (row * HS + q * 4) * 4, hb + c * 4);
            }
            asm volatile("cp.async.commit_group;\n");
        }

        const float* shb = &shbase[(g % NBUF) * 64 * HS];

        // ---- load all A fragments up front (8x LDS.128, max MLP) ----
        float4 fAr[4], fBr[4];
#pragma unroll
        for (int q = 0; q < 4; ++q) {
            const int cb = 16 * q + 4 * tig;
            fAr[q] = *reinterpret_cast<const float4*>(&shb[rA * HS + cb]);
            fBr[q] = *reinterpret_cast<const float4*>(&shb[rB * HS + cb]);
        }

        // ---- fp32 dot partials ----
        float pd0 = 0.f, pd1 = 0.f;
#pragma unroll
        for (int q = 0; q < 4; ++q) {
            pd0 = fmaf(fAr[q].x, vv[q].x, fmaf(fAr[q].y, vv[q].y,
                  fmaf(fAr[q].z, vv[q].z, fmaf(fAr[q].w, vv[q].w, pd0))));
            pd1 = fmaf(fBr[q].x, vv[q].x, fmaf(fBr[q].y, vv[q].y,
                  fmaf(fBr[q].z, vv[q].z, fmaf(fBr[q].w, vv[q].w, pd1))));
        }

        // ---- GEMM (fp16, unscaled, 8 n-tiles) ----
        float acc[8][4];
#pragma unroll
        for (int nt = 0; nt < 8; ++nt)
#pragma unroll
            for (int k = 0; k < 4; ++k) acc[nt][k] = 0.f;

#pragma unroll
        for (int q = 0; q < 4; ++q) {
            unsigned a0 = h2u(__floats2half2_rn(fAr[q].x, fAr[q].y));
            unsigned a1 = h2u(__floats2half2_rn(fBr[q].x, fBr[q].y));
            unsigned a2 = h2u(__floats2half2_rn(fAr[q].z, fAr[q].w));
            unsigned a3 = h2u(__floats2half2_rn(fBr[q].z, fBr[q].w));
#pragma unroll
            for (int nt = 0; nt < 8; ++nt) {
                asm volatile(
                    "mma.sync.aligned.m16n8k16.row.col.f32.f16.f16.f32 "
                    "{%0,%1,%2,%3}, {%4,%5,%6,%7}, {%8,%9}, {%0,%1,%2,%3};"
                    : "+f"(acc[nt][0]), "+f"(acc[nt][1]),
                      "+f"(acc[nt][2]), "+f"(acc[nt][3])
                    : "r"(a0), "r"(a1), "r"(a2), "r"(a3),
                      "r"(bfr[q][nt][0]), "r"(bfr[q][nt][1]));
            }
        }

        // ---- reduce dots over tig lanes; publish (parity-buffered) ----
        pd0 += __shfl_xor_sync(0xffffffffu, pd0, 1);
        pd0 += __shfl_xor_sync(0xffffffffu, pd0, 2);
        pd1 += __shfl_xor_sync(0xffffffffu, pd1, 1);
        pd1 += __shfl_xor_sync(0xffffffffu, pd1, 2);
        float* sd = sdots + (g & 1) * 64;
        if (tig == 0) {
            sd[rA] = pd0;
            sd[rB] = pd1;
        }
        __syncthreads();   // bar B: sdots complete

        // ---- warp-local softmax over rows 1..63 ----
        float x0 = (lane >= 1) ? sd[lane] : -1e30f;
        float x1 = sd[lane + 32];
        float m = fmaxf(x0, x1);
#pragma unroll
        for (int off = 16; off; off >>= 1)
            m = fmaxf(m, __shfl_xor_sync(0xffffffffu, m, off));
        float e0s = (lane >= 1) ? __expf(x0 - m) : 0.f;
        float e1s = __expf(x1 - m);
        float s = e0s + e1s;
#pragma unroll
        for (int off = 16; off; off >>= 1)
            s += __shfl_xor_sync(0xffffffffu, s, off);
        const float inv = 1.f / s;

        const float fA = (rA == 0) ? 1.f : __expf(pd0 - m) * inv;
        const float fB = __expf(pd1 - m) * inv;   // rB >= 8, never robot

        // ---- epilogue: scale, elu, 8x STG.128 ----
        float* ob = out + base + (size_t)g * 4096;
#pragma unroll
        for (int p = 0; p < 4; ++p) {
            const int col = p * 16 + tig * 4;
            float4 v0 = make_float4(elu1(acc[2 * p][0] * fA),
                                    elu1(acc[2 * p][1] * fA),
                                    elu1(acc[2 * p + 1][0] * fA),
                                    elu1(acc[2 * p + 1][1] * fA));
            float4 v1 = make_float4(elu1(acc[2 * p][2] * fB),
                                    elu1(acc[2 * p][3] * fB),
                                    elu1(acc[2 * p + 1][2] * fB),
                                    elu1(acc[2 * p + 1][3] * fB));
            *reinterpret_cast<float4*>(ob + rA * 64 + col) = v0;
            *reinterpret_cast<float4*>(ob + rB * 64 + col) = v1;
        }
    }
}

extern "C" void kernel_launch(void* const* d_in, const int* in_sizes, int n_in,
                              void* d_out, int out_size) {
    const float* h = (const float*)d_in[0];   // (16384, 64, 64) f32
    const float* W = (const float*)d_in[1];   // (64, 64) f32
    const float* a = (const float*)d_in[2];   // (128, 1) f32
    float* out = (float*)d_out;               // (16384, 64, 64) f32

    const int smem_bytes = SMEM_FLOATS * sizeof(float);   // ~62 KB
    cudaFuncSetAttribute(gat_fused_kernel,
                         cudaFuncAttributeMaxDynamicSharedMemorySize, smem_bytes);
    gat_fused_kernel<<<16384 / GB, 128, smem_bytes>>>(h, W, a, out);
}